// round 15
// baseline (speedup 1.0000x reference)
#include <cuda_runtime.h>
#include <cuda_fp16.h>
#include <math.h>
#include <stdint.h>

#define BATCH   2
#define SEQ     2048
#define DMODEL  2048
#define NHEADS  16
#define DK      128
#define M_TOT   (BATCH*SEQ)   // 4096
#define KC      4096          // corr K (interleaved hi/lo pairs)

// ---------------- fp32 scratch ----------------
__device__ float g_q [M_TOT*DMODEL];
__device__ float g_k [M_TOT*DMODEL];
__device__ float g_v [M_TOT*DMODEL];
__device__ float g_ao[M_TOT*DMODEL];

// ---------------- fp16 operands: main (hi) + corr (interleaved) ------------
__device__ __half g_xm [(size_t)M_TOT*DMODEL];    // Ah
__device__ __half g_xc [(size_t)M_TOT*KC];        // (Ah,Al) per k
__device__ __half g_aom[(size_t)M_TOT*DMODEL];
__device__ __half g_aoc[(size_t)M_TOT*KC];
__device__ __half g_wm [(size_t)4*DMODEL*DMODEL]; // Wh
__device__ __half g_wc [(size_t)4*DMODEL*KC];     // (Wl,Wh) per k

// ---------------- fp16 split operands for attention ------------------------
__device__ __half g_qh [M_TOT*DMODEL];
__device__ __half g_ql [M_TOT*DMODEL];
__device__ __half g_kh [M_TOT*DMODEL];
__device__ __half g_kl [M_TOT*DMODEL];
__device__ __half g_vth[M_TOT*DMODEL];   // [b,h,d,s]
__device__ __half g_vtl[M_TOT*DMODEL];   // [b,h,d,s]

// ============================ PTX helpers ==================================
__device__ __forceinline__ uint32_t smem_u32(const void* p) {
    uint32_t a;
    asm("{ .reg .u64 t; cvta.to.shared.u64 t, %1; cvt.u32.u64 %0, t; }"
        : "=r"(a) : "l"(p));
    return a;
}
__device__ __forceinline__ void cp_async16(uint32_t dst, const void* src) {
    asm volatile("cp.async.cg.shared.global [%0], [%1], 16;"
                 :: "r"(dst), "l"(src) : "memory");
}
#define CP_COMMIT()  asm volatile("cp.async.commit_group;" ::: "memory")
#define CP_WAIT1()   asm volatile("cp.async.wait_group 1;" ::: "memory")
#define CP_WAIT0()   asm volatile("cp.async.wait_group 0;" ::: "memory")

#define LDSM_X4(r, addr) \
    asm volatile("ldmatrix.sync.aligned.m8n8.x4.shared.b16 {%0,%1,%2,%3}, [%4];" \
        : "=r"((r)[0]), "=r"((r)[1]), "=r"((r)[2]), "=r"((r)[3]) : "r"(addr))

#define MMA16816(d, a, b) \
    asm volatile("mma.sync.aligned.m16n8k16.row.col.f32.f16.f16.f32 " \
        "{%0,%1,%2,%3}, {%4,%5,%6,%7}, {%8,%9}, {%0,%1,%2,%3};" \
        : "+f"((d)[0]), "+f"((d)[1]), "+f"((d)[2]), "+f"((d)[3]) \
        : "r"((a)[0]), "r"((a)[1]), "r"((a)[2]), "r"((a)[3]), \
          "r"((b)[0]), "r"((b)[1]))

// fp16-accumulate variant (corrections only; values ~2^-11 of main term)
#define MMA16816F16(d, a, b) \
    asm volatile("mma.sync.aligned.m16n8k16.row.col.f16.f16.f16.f16 " \
        "{%0,%1}, {%2,%3,%4,%5}, {%6,%7}, {%0,%1};" \
        : "+r"((d)[0]), "+r"((d)[1]) \
        : "r"((a)[0]), "r"((a)[1]), "r"((a)[2]), "r"((a)[3]), \
          "r"((b)[0]), "r"((b)[1]))

// ===========================================================================
// Split conversion: fp32 [rows,2048] -> main fp16 [rows,2048] (hi)
//                                    + corr fp16 [rows,4096] interleaved.
// act=1 (A side):  corr[2k]=h, corr[2k+1]=l
// act=0 (W side):  corr[2k]=l, corr[2k+1]=h
// (corr dot product: Ah*Wl + Al*Wh — the two cross terms.)
// ===========================================================================
__device__ __forceinline__ void split4(const float* f, __half* h, __half* l) {
#pragma unroll
    for (int i = 0; i < 4; ++i) {
        h[i] = __float2half_rn(f[i]);
        l[i] = __float2half_rn(f[i] - __half2float(h[i]));
    }
}

__global__ void conv_split2(const float* __restrict__ src,
                            __half* __restrict__ mn, __half* __restrict__ cr,
                            int act)
{
    int p   = blockIdx.x * blockDim.x + threadIdx.x;
    int row = p >> 9;
    int kq  = (p & 511) * 4;

    float4 v = *(const float4*)(src + ((size_t)row << 11) + kq);
    float f[4] = {v.x, v.y, v.z, v.w};
    __half h[4], l[4];
    split4(f, h, l);

    *(uint2*)(mn + ((size_t)row << 11) + kq) = *(uint2*)h;

    __half c[8];
    if (act) {
#pragma unroll
        for (int i = 0; i < 4; ++i) { c[2*i] = h[i]; c[2*i+1] = l[i]; }
    } else {
#pragma unroll
        for (int i = 0; i < 4; ++i) { c[2*i] = l[i]; c[2*i+1] = h[i]; }
    }
    *(uint4*)(cr + ((size_t)row << 12) + 2*kq) = *(uint4*)c;
}

// All 4 weights in one launch (blockIdx.y selects the weight)
__global__ void conv_split2_w(const float* __restrict__ w0, const float* __restrict__ w1,
                              const float* __restrict__ w2, const float* __restrict__ w3,
                              __half* __restrict__ mn, __half* __restrict__ cr)
{
    int z = blockIdx.y;
    const float* src = (z == 0) ? w0 : (z == 1) ? w1 : (z == 2) ? w2 : w3;
    int p   = blockIdx.x * blockDim.x + threadIdx.x;
    int row = p >> 9;
    int kq  = (p & 511) * 4;

    float4 v = *(const float4*)(src + ((size_t)row << 11) + kq);
    float f[4] = {v.x, v.y, v.z, v.w};
    __half h[4], l[4];
    split4(f, h, l);

    __half* mz = mn + (size_t)z * DMODEL * DMODEL;
    __half* cz = cr + (size_t)z * DMODEL * KC;
    *(uint2*)(mz + ((size_t)row << 11) + kq) = *(uint2*)h;

    __half c[8];
#pragma unroll
    for (int i = 0; i < 4; ++i) { c[2*i] = l[i]; c[2*i+1] = h[i]; }
    *(uint4*)(cz + ((size_t)row << 12) + 2*kq) = *(uint4*)c;
}

// ===========================================================================
// fp16 mma.sync GEMM, split accumulators:
//   phase 1: 64 corr k-tiles (K'=4096, (Ah,Al)x(Wl,Wh)) -> fp16 accum
//   phase 2: 32 main k-tiles (K=2048, Ah x Wh)          -> fp32 accum,
//            initialized by promoting the fp16 corr accumulator.
// BM=BN=128, BK=64, 8 warps (2x4), warp tile 64x32, 3-stage cp.async.
// N-concatenated outputs: sel = n0>>11 -> C0/C1/C2; W row = n0&2047.
// ===========================================================================
#define CKT      64
#define MKT      32
#define TOT_KT   96
#define STAGES   3
#define STG_B    32768u
#define GEMM_SMEM (STAGES*STG_B)

__global__ __launch_bounds__(256, 2)
void gemm_mma2(const __half* __restrict__ Am, const __half* __restrict__ Ac,
               const __half* __restrict__ Wm, const __half* __restrict__ Wc,
               const float* __restrict__ bias,
               float* __restrict__ C0, float* __restrict__ C1,
               float* __restrict__ C2)
{
    extern __shared__ unsigned char smraw[];
    const uint32_t sbase = smem_u32(smraw);

    const int tid  = threadIdx.x;
    const int lane = tid & 31, wid = tid >> 5;
    const int wm = wid & 1, wn = wid >> 1;
    const int m0 = blockIdx.y * 128, n0 = blockIdx.x * 128;
    const int wsel = n0 >> 11;
    const int nr0  = n0 & (DMODEL - 1);

    const int ldr = tid >> 3;
    const int ldc = tid & 7;
    const __half* amp = Am + (size_t)(m0 + ldr) * DMODEL + ldc * 8;
    const __half* acp = Ac + (size_t)(m0 + ldr) * KC     + ldc * 8;
    const __half* wmp = Wm + (size_t)wsel * DMODEL * DMODEL
                           + (size_t)(nr0 + ldr) * DMODEL + ldc * 8;
    const __half* wcp = Wc + (size_t)wsel * DMODEL * KC
                           + (size_t)(nr0 + ldr) * KC     + ldc * 8;
    const uint32_t sw_off = (uint32_t)(ldr * 8 + (ldc ^ (ldr & 7))) * 16;

    uint32_t cacc[4][4][2];
#pragma unroll
    for (int mi = 0; mi < 4; ++mi)
#pragma unroll
        for (int ni = 0; ni < 4; ++ni) { cacc[mi][ni][0] = 0u; cacc[mi][ni][1] = 0u; }
    float acc[4][4][4];

    const int arow = wm * 64 + (lane & 15);
    const int acb  = lane >> 4;
    const int brow = wn * 32 + (lane & 7) + ((lane >> 4) << 3);
    const int bcb  = (lane >> 3) & 1;

    auto load_stage = [&](int slot, int ti) {
        uint32_t s = sbase + (uint32_t)slot * STG_B;
        const __half *ag, *wg; size_t rstep;
        if (ti < CKT) { ag = acp + ti * 64;          wg = wcp + ti * 64;
                        rstep = (size_t)32 * KC; }
        else          { ag = amp + (ti - CKT) * 64;  wg = wmp + (ti - CKT) * 64;
                        rstep = (size_t)32 * DMODEL; }
#pragma unroll
        for (int r4 = 0; r4 < 4; ++r4) {
            uint32_t o = sw_off + (uint32_t)r4 * 32 * 128;
            cp_async16(s + o,          ag + r4 * rstep);
            cp_async16(s + 16384u + o, wg + r4 * rstep);
        }
    };

    auto lds_frags = [&](int slot, int ks, uint32_t a[4][4], uint32_t b[4][2]) {
        uint32_t s  = sbase + (uint32_t)slot * STG_B;
        uint32_t sb = s + 16384u;
#pragma unroll
        for (int mi = 0; mi < 4; ++mi) {
            int row = arow + mi * 16;
            uint32_t addr = s + (uint32_t)(row * 8 + ((2*ks + acb) ^ (row & 7))) * 16;
            LDSM_X4(a[mi], addr);
        }
#pragma unroll
        for (int nj = 0; nj < 2; ++nj) {
            int row = brow + nj * 16;
            uint32_t addr = sb + (uint32_t)(row * 8 + ((2*ks + bcb) ^ (row & 7))) * 16;
            uint32_t r[4];
            LDSM_X4(r, addr);
            b[nj*2+0][0] = r[0]; b[nj*2+0][1] = r[1];
            b[nj*2+1][0] = r[2]; b[nj*2+1][1] = r[3];
        }
    };

    load_stage(0, 0); CP_COMMIT();
    load_stage(1, 1); CP_COMMIT();

    // ---- phase 1: corrections, fp16 accumulate ----
    for (int ti = 0; ti < CKT; ++ti) {
        CP_WAIT1();
        __syncthreads();
        load_stage((ti + 2) % STAGES, ti + 2); CP_COMMIT();
#pragma unroll
        for (int ks = 0; ks < 4; ++ks) {
            uint32_t a[4][4], b[4][2];
            lds_frags(ti % STAGES, ks, a, b);
#pragma unroll
            for (int mi = 0; mi < 4; ++mi)
#pragma unroll
                for (int ni = 0; ni < 4; ++ni)
                    MMA16816F16(cacc[mi][ni], a[mi], b[ni]);
        }
    }

    // ---- promote corr fp16 -> fp32 accumulators ----
#pragma unroll
    for (int mi = 0; mi < 4; ++mi)
#pragma unroll
        for (int ni = 0; ni < 4; ++ni) {
            float2 lo = __half22float2(*(__half2*)&cacc[mi][ni][0]);
            float2 hi = __half22float2(*(__half2*)&cacc[mi][ni][1]);
            acc[mi][ni][0] = lo.x; acc[mi][ni][1] = lo.y;
            acc[mi][ni][2] = hi.x; acc[mi][ni][3] = hi.y;
        }

    // ---- phase 2: main product, fp32 accumulate ----
    for (int ti = CKT; ti < TOT_KT; ++ti) {
        CP_WAIT1();
        __syncthreads();
        int pf = ti + 2;
        if (pf < TOT_KT) { load_stage(pf % STAGES, pf); CP_COMMIT(); }
#pragma unroll
        for (int ks = 0; ks < 4; ++ks) {
            uint32_t a[4][4], b[4][2];
            lds_frags(ti % STAGES, ks, a, b);
#pragma unroll
            for (int mi = 0; mi < 4; ++mi)
#pragma unroll
                for (int ni = 0; ni < 4; ++ni)
                    MMA16816(acc[mi][ni], a[mi], b[ni]);
        }
    }

    float* Cx = (wsel == 0) ? C0 : ((wsel == 1) ? C1 : C2);

#pragma unroll
    for (int mi = 0; mi < 4; ++mi) {
        int row = m0 + wm * 64 + mi * 16 + (lane >> 2);
#pragma unroll
        for (int ni = 0; ni < 4; ++ni) {
            int col = nr0 + wn * 32 + ni * 8 + (lane & 3) * 2;
            float2 v0 = {acc[mi][ni][0], acc[mi][ni][1]};
            float2 v1 = {acc[mi][ni][2], acc[mi][ni][3]};
            if (bias) {
                float b0 = __ldg(bias + col), b1 = __ldg(bias + col + 1);
                v0.x += b0; v0.y += b1; v1.x += b0; v1.y += b1;
            }
            *(float2*)(Cx + (size_t) row      * DMODEL + col) = v0;
            *(float2*)(Cx + (size_t)(row + 8) * DMODEL + col) = v1;
        }
    }
}

// ---------------------------------------------------------------------------
// Fused RoPE + hi/lo split (unchanged, verified R14)
// ---------------------------------------------------------------------------
__global__ void rope_split(const float* __restrict__ q, const float* __restrict__ k,
                           __half* __restrict__ qh, __half* __restrict__ ql,
                           __half* __restrict__ kh, __half* __restrict__ kl)
{
    int p = blockIdx.x * blockDim.x + threadIdx.x;
    if (p >= M_TOT * NHEADS * (DK/2)) return;
    int i = p & 63;
    int h = (p >> 6) & 15;
    int m = p >> 10;
    int s = m & (SEQ - 1);

    float freq = expf(-(float)(2*i) * 0.07195578415f);
    float ang  = (float)s * freq;
    float sn, cs;
    sincosf(ang, &sn, &cs);

    size_t base = (size_t)m * DMODEL + h*DK + 2*i;
    float2 qv = *(const float2*)(q + base);
    float2 kv = *(const float2*)(k + base);
    float q0 = qv.x*cs - qv.y*sn, q1 = qv.x*sn + qv.y*cs;
    float k0 = kv.x*cs - kv.y*sn, k1 = kv.x*sn + kv.y*cs;

    __half2 qhh = __floats2half2_rn(q0, q1);
    float2  qhf = __half22float2(qhh);
    __half2 qll = __floats2half2_rn(q0 - qhf.x, q1 - qhf.y);
    __half2 khh = __floats2half2_rn(k0, k1);
    float2  khf = __half22float2(khh);
    __half2 kll = __floats2half2_rn(k0 - khf.x, k1 - khf.y);

    *(__half2*)(qh + base) = qhh;
    *(__half2*)(ql + base) = qll;
    *(__half2*)(kh + base) = khh;
    *(__half2*)(kl + base) = kll;
}

// ---------------------------------------------------------------------------
// V transpose + split (unchanged, verified)
// ---------------------------------------------------------------------------
__global__ void vt_split(const float* __restrict__ v,
                         __half* __restrict__ vth, __half* __restrict__ vtl)
{
    __shared__ float sm[64][129];
    int s0 = blockIdx.x * 64;
    int bh = blockIdx.y;
    int b  = bh >> 4, h = bh & 15;
    const float* src = v + (size_t)(b*SEQ)*DMODEL + h*DK;

    for (int i = threadIdx.x; i < 64*32; i += 256) {
        int r = i >> 5, c4 = (i & 31) * 4;
        float4 vv = *(const float4*)(src + (size_t)(s0 + r) * DMODEL + c4);
        sm[r][c4] = vv.x; sm[r][c4+1] = vv.y; sm[r][c4+2] = vv.z; sm[r][c4+3] = vv.w;
    }
    __syncthreads();

    int d  = threadIdx.x >> 1;
    int j0 = (threadIdx.x & 1) * 32;
    size_t obase = ((size_t)bh * DK + d) * SEQ + s0 + j0;
#pragma unroll
    for (int jj = 0; jj < 32; jj += 8) {
        __half hh[8], ll[8];
#pragma unroll
        for (int u = 0; u < 8; ++u) {
            float f = sm[j0 + jj + u][d];
            __half x = __float2half_rn(f);
            hh[u] = x;
            ll[u] = __float2half_rn(f - __half2float(x));
        }
        *(uint4*)(vth + obase + jj) = *(uint4*)hh;
        *(uint4*)(vtl + obase + jj) = *(uint4*)ll;
    }
}

// ===========================================================================
// mma.sync causal flash attention; main product fp32-accum, corrections
// fp16-accum (promoted per tile).  BQ=128, BKV=64, Dk=128, 192 KB smem.
// ===========================================================================
#define ABQ   128
#define ABKV  64
#define AQH_O 0u
#define AQL_O 32768u
#define AKV_O 65536u
#define AKV_STG 65536u
#define AKH_O 0u
#define AKL_O 16384u
#define AVH_O 32768u
#define AVL_O 49152u
#define ATTN_SMEM (65536u + 2u*65536u)

__global__ __launch_bounds__(256, 1)
void flash_attn_mma(const __half* __restrict__ qh, const __half* __restrict__ ql,
                    const __half* __restrict__ kh, const __half* __restrict__ kl,
                    const __half* __restrict__ vth, const __half* __restrict__ vtl,
                    float* __restrict__ Og)
{
    extern __shared__ unsigned char smraw[];
    const uint32_t sb = smem_u32(smraw);
    const int tid = threadIdx.x, lane = tid & 31, wid = tid >> 5;
    const int qblk = gridDim.x - 1 - blockIdx.x;
    const int q0 = qblk * ABQ;
    const int bh = blockIdx.y;
    const int b  = bh >> 4, h = bh & 15;
    const size_t qk_base = (size_t)(b*SEQ)*DMODEL + h*DK;
    const size_t vt_base = (size_t)bh * DK * SEQ;

    const int ntiles = q0 / ABKV + 2;
    const int g = lane >> 2, t4 = lane & 3;
    const int wq0 = q0 + wid * 16;

    {   // Q tiles
        int c  = tid & 15;
        int r0 = tid >> 4;
#pragma unroll
        for (int rr = 0; rr < 8; ++rr) {
            int row = r0 + rr * 16;
            uint32_t dst = (uint32_t)(row * 16 + (c ^ (row & 7))) * 16;
            cp_async16(sb + AQH_O + dst,
                       qh + qk_base + (size_t)(q0 + row) * DMODEL + c * 8);
            cp_async16(sb + AQL_O + dst,
                       ql + qk_base + (size_t)(q0 + row) * DMODEL + c * 8);
        }
    }
    auto load_kv = [&](int st, int tl) {
        uint32_t s = sb + AKV_O + (uint32_t)st * AKV_STG;
        int k0 = tl * ABKV;
        {
            int c  = tid & 15;
            int r0 = tid >> 4;
#pragma unroll
            for (int rr = 0; rr < 4; ++rr) {
                int row = r0 + rr * 16;
                uint32_t dst = (uint32_t)(row * 16 + (c ^ (row & 7))) * 16;
                cp_async16(s + AKH_O + dst,
                           kh + qk_base + (size_t)(k0 + row) * DMODEL + c * 8);
                cp_async16(s + AKL_O + dst,
                           kl + qk_base + (size_t)(k0 + row) * DMODEL + c * 8);
            }
        }
        {
            int c  = tid & 7;
            int r0 = tid >> 3;
#pragma unroll
            for (int rr = 0; rr < 4; ++rr) {
                int row = r0 + rr * 32;
                uint32_t dst = (uint32_t)(row * 8 + (c ^ (row & 7))) * 16;
                cp_async16(s + AVH_O + dst,
                           vth + vt_base + (size_t)row * SEQ + k0 + c * 8);
                cp_async16(s + AVL_O + dst,
                           vtl + vt_base + (size_t)row * SEQ + k0 + c * 8);
            }
        }
    };

    load_kv(0, 0); CP_COMMIT();

    float o[16][4];
#pragma unroll
    for (int nt = 0; nt < 16; ++nt)
#pragma unroll
        for (int r = 0; r < 4; ++r) o[nt][r] = 0.f;
    float m0 = -1e30f, m1 = -1e30f, den0 = 0.f, den1 = 0.f;
    const float scale = 0.08838834764831845f;

    for (int tl = 0; tl < ntiles; ++tl) {
        int k0 = tl * ABKV;
        if (tl + 1 < ntiles) { load_kv((tl + 1) & 1, tl + 1); CP_COMMIT(); CP_WAIT1(); }
        else                 { CP_WAIT0(); }
        __syncthreads();

        uint32_t st = sb + AKV_O + (uint32_t)(tl & 1) * AKV_STG;

        if (k0 <= wq0 + 15) {
            // -------- S = Q K^T: main fp32 + corr fp16 --------
            float s4[8][4];
            uint32_t sc[8][2];
#pragma unroll
            for (int nt = 0; nt < 8; ++nt) {
#pragma unroll
                for (int r = 0; r < 4; ++r) s4[nt][r] = 0.f;
                sc[nt][0] = 0u; sc[nt][1] = 0u;
            }

            const int arow = wid * 16 + (lane & 15);
            const int brow0 = (lane & 7) + ((lane >> 4) << 3);
            const int bcbit = (lane >> 3) & 1;
#pragma unroll
            for (int ks = 0; ks < 8; ++ks) {
                int ach = 2 * ks + (lane >> 4);
                uint32_t qoff = (uint32_t)(arow * 16 + (ach ^ (arow & 7))) * 16;
                uint32_t aH[4], aL[4];
                LDSM_X4(aH, sb + AQH_O + qoff);
                LDSM_X4(aL, sb + AQL_O + qoff);
#pragma unroll
                for (int nj = 0; nj < 4; ++nj) {
                    int brow = brow0 + nj * 16;
                    int bch  = 2 * ks + bcbit;
                    uint32_t koff = (uint32_t)(brow * 16 + (bch ^ (brow & 7))) * 16;
                    uint32_t rH[4], rL[4];
                    LDSM_X4(rH, st + AKH_O + koff);
                    LDSM_X4(rL, st + AKL_O + koff);
                    uint32_t bH0[2] = {rH[0], rH[1]}, bH1[2] = {rH[2], rH[3]};
                    uint32_t bL0[2] = {rL[0], rL[1]}, bL1[2] = {rL[2], rL[3]};
                    MMA16816(s4[2*nj],   aH, bH0);       // main
                    MMA16816(s4[2*nj+1], aH, bH1);
                    MMA16816F16(sc[2*nj],   aH, bL0);    // corr Qh*Kl
                    MMA16816F16(sc[2*nj+1], aH, bL1);
                    MMA16816F16(sc[2*nj],   aL, bH0);    // corr Ql*Kh
                    MMA16816F16(sc[2*nj+1], aL, bH1);
                }
            }
#pragma unroll
            for (int nt = 0; nt < 8; ++nt) {
                float2 lo = __half22float2(*(__half2*)&sc[nt][0]);
                float2 hi = __half22float2(*(__half2*)&sc[nt][1]);
                s4[nt][0] += lo.x; s4[nt][1] += lo.y;
                s4[nt][2] += hi.x; s4[nt][3] += hi.y;
            }

            // -------- scale + causal mask --------
            const bool domask = (k0 + ABKV - 1 > wq0);
            const int r0g = wq0 + g, r1g = wq0 + 8 + g;
#pragma unroll
            for (int nt = 0; nt < 8; ++nt) {
#pragma unroll
                for (int r = 0; r < 4; ++r) s4[nt][r] *= scale;
                if (domask) {
                    int c0 = k0 + nt * 8 + 2 * t4;
                    if (c0     > r0g) s4[nt][0] = -1e30f;
                    if (c0 + 1 > r0g) s4[nt][1] = -1e30f;
                    if (c0     > r1g) s4[nt][2] = -1e30f;
                    if (c0 + 1 > r1g) s4[nt][3] = -1e30f;
                }
            }

            // -------- online softmax --------
            float mx0 = -1e30f, mx1 = -1e30f;
#pragma unroll
            for (int nt = 0; nt < 8; ++nt) {
                mx0 = fmaxf(mx0, fmaxf(s4[nt][0], s4[nt][1]));
                mx1 = fmaxf(mx1, fmaxf(s4[nt][2], s4[nt][3]));
            }
            mx0 = fmaxf(mx0, __shfl_xor_sync(0xffffffffu, mx0, 1));
            mx0 = fmaxf(mx0, __shfl_xor_sync(0xffffffffu, mx0, 2));
            mx1 = fmaxf(mx1, __shfl_xor_sync(0xffffffffu, mx1, 1));
            mx1 = fmaxf(mx1, __shfl_xor_sync(0xffffffffu, mx1, 2));
            float mn0 = fmaxf(m0, mx0), mn1 = fmaxf(m1, mx1);
            float al0 = __expf(m0 - mn0), al1 = __expf(m1 - mn1);
            m0 = mn0; m1 = mn1;

            float sum0 = 0.f, sum1 = 0.f;
            uint32_t phA[8], phB[8], plA[8], plB[8];
#pragma unroll
            for (int nt = 0; nt < 8; ++nt) {
                float e0 = __expf(s4[nt][0] - mn0), e1 = __expf(s4[nt][1] - mn0);
                float e2 = __expf(s4[nt][2] - mn1), e3 = __expf(s4[nt][3] - mn1);
                sum0 += e0 + e1; sum1 += e2 + e3;
                __half2 h0 = __floats2half2_rn(e0, e1);
                __half2 h1 = __floats2half2_rn(e2, e3);
                float2 f0 = __half22float2(h0), f1 = __half22float2(h1);
                __half2 q0h = __floats2half2_rn(e0 - f0.x, e1 - f0.y);
                __half2 q1h = __floats2half2_rn(e2 - f1.x, e3 - f1.y);
                phA[nt] = *(uint32_t*)&h0;  phB[nt] = *(uint32_t*)&h1;
                plA[nt] = *(uint32_t*)&q0h; plB[nt] = *(uint32_t*)&q1h;
            }
            sum0 += __shfl_xor_sync(0xffffffffu, sum0, 1);
            sum0 += __shfl_xor_sync(0xffffffffu, sum0, 2);
            sum1 += __shfl_xor_sync(0xffffffffu, sum1, 1);
            sum1 += __shfl_xor_sync(0xffffffffu, sum1, 2);
            den0 = den0 * al0 + sum0;
            den1 = den1 * al1 + sum1;

#pragma unroll
            for (int nt = 0; nt < 16; ++nt) {
                o[nt][0] *= al0; o[nt][1] *= al0;
                o[nt][2] *= al1; o[nt][3] *= al1;
            }

            // -------- O += P V: main fp32 + corr fp16 (per-tile promote) ----
            uint32_t oc[16][2];
#pragma unroll
            for (int nt = 0; nt < 16; ++nt) { oc[nt][0] = 0u; oc[nt][1] = 0u; }
#pragma unroll
            for (int ks = 0; ks < 4; ++ks) {
                uint32_t aH[4] = {phA[2*ks], phB[2*ks], phA[2*ks+1], phB[2*ks+1]};
                uint32_t aL[4] = {plA[2*ks], plB[2*ks], plA[2*ks+1], plB[2*ks+1]};
#pragma unroll
                for (int nj = 0; nj < 8; ++nj) {
                    int brow = brow0 + nj * 16;
                    int bch  = 2 * ks + bcbit;
                    uint32_t voff = (uint32_t)(brow * 8 + (bch ^ (brow & 7))) * 16;
                    uint32_t rH[4], rL[4];
                    LDSM_X4(rH, st + AVH_O + voff);
                    LDSM_X4(rL, st + AVL_O + voff);
                    uint32_t bH0[2] = {rH[0], rH[1]}, bH1[2] = {rH[2], rH[3]};
                    uint32_t bL0[2] = {rL[0], rL[1]}, bL1[2] = {rL[2], rL[3]};
                    MMA16816(o[2*nj],   aH, bH0);        // main
                    MMA16816(o[2*nj+1], aH, bH1);
                    MMA16816F16(oc[2*nj],   aH, bL0);    // corr Ph*Vl
                    MMA16816F16(oc[2*nj+1], aH, bL1);
                    MMA16816F16(oc[2*nj],   aL, bH0);    // corr Pl*Vh
                    MMA16816F16(oc[2*nj+1], aL, bH1);
                }
            }
#pragma unroll
            for (int nt = 0; nt < 16; ++nt) {
                float2 lo = __half22float2(*(__half2*)&oc[nt][0]);
                float2 hi = __half22float2(*(__half2*)&oc[nt][1]);
                o[nt][0] += lo.x; o[nt][1] += lo.y;
                o[nt][2] += hi.x; o[nt][3] += hi.y;
            }
        }
        __syncthreads();
    }

    // -------- epilogue --------
    float inv0 = 1.f / den0, inv1 = 1.f / den1;
    int row0 = wq0 + g;
    float* O0 = Og + (size_t)(b*SEQ + row0) * DMODEL + h * DK;
    float* O1 = O0 + (size_t)8 * DMODEL;
#pragma unroll
    for (int nt = 0; nt < 16; ++nt) {
        int col = nt * 8 + 2 * t4;
        float2 v0 = {o[nt][0] * inv0, o[nt][1] * inv0};
        float2 v1 = {o[nt][2] * inv1, o[nt][3] * inv1};
        *(float2*)(O0 + col) = v0;
        *(float2*)(O1 + col) = v1;
    }
}

// ---------------------------------------------------------------------------
extern "C" void kernel_launch(void* const* d_in, const int* in_sizes, int n_in,
                              void* d_out, int out_size)
{
    (void)in_sizes; (void)n_in; (void)out_size;
    const float* x  = (const float*)d_in[0];
    const float* wq = (const float*)d_in[1];
    const float* wk = (const float*)d_in[2];
    const float* wv = (const float*)d_in[3];
    const float* wo = (const float*)d_in[4];
    const float* bo = (const float*)d_in[5];
    float* out = (float*)d_out;

    float *q, *k, *v, *ao;
    __half *xm, *xc, *aom, *aoc, *wm, *wc, *qh, *ql, *kh, *kl, *vth, *vtl;
    cudaGetSymbolAddress((void**)&q,   g_q);
    cudaGetSymbolAddress((void**)&k,   g_k);
    cudaGetSymbolAddress((void**)&v,   g_v);
    cudaGetSymbolAddress((void**)&ao,  g_ao);
    cudaGetSymbolAddress((void**)&xm,  g_xm);
    cudaGetSymbolAddress((void**)&xc,  g_xc);
    cudaGetSymbolAddress((void**)&aom, g_aom);
    cudaGetSymbolAddress((void**)&aoc, g_aoc);
    cudaGetSymbolAddress((void**)&wm,  g_wm);
    cudaGetSymbolAddress((void**)&wc,  g_wc);
    cudaGetSymbolAddress((void**)&qh,  g_qh);
    cudaGetSymbolAddress((void**)&ql,  g_ql);
    cudaGetSymbolAddress((void**)&kh,  g_kh);
    cudaGetSymbolAddress((void**)&kl,  g_kl);
    cudaGetSymbolAddress((void**)&vth, g_vth);
    cudaGetSymbolAddress((void**)&vtl, g_vtl);

    conv_split2<<<(M_TOT*512)/256, 256>>>(x, xm, xc, 1);
    conv_split2_w<<<dim3((DMODEL*512)/256, 4), 256>>>(wq, wk, wv, wo, wm, wc);

    cudaFuncSetAttribute(gemm_mma2, cudaFuncAttributeMaxDynamicSharedMemorySize,
                         (int)GEMM_SMEM);
    // fused QKV: N = 6144 over concatenated wq|wk|wv main/corr expansions
    dim3 gqkv(3*DMODEL/128, M_TOT/128);   // (48, 32)
    gemm_mma2<<<gqkv, 256, GEMM_SMEM>>>(xm, xc, wm, wc, nullptr, q, k, v);

    int pairs = M_TOT * NHEADS * (DK/2);
    rope_split<<<(pairs + 255) / 256, 256>>>(q, k, qh, ql, kh, kl);
    vt_split<<<dim3(SEQ/64, BATCH*NHEADS), 256>>>(v, vth, vtl);

    cudaFuncSetAttribute(flash_attn_mma, cudaFuncAttributeMaxDynamicSharedMemorySize,
                         (int)ATTN_SMEM);
    dim3 agrid(SEQ/ABQ, BATCH*NHEADS);   // (16, 32)
    flash_attn_mma<<<agrid, 256, ATTN_SMEM>>>(qh, ql, kh, kl, vth, vtl, ao);

    conv_split2<<<(M_TOT*512)/256, 256>>>(ao, aom, aoc, 1);
    dim3 gout(DMODEL/128, M_TOT/128);     // (16, 32)
    gemm_mma2<<<gout, 256, GEMM_SMEM>>>(aom, aoc,
                                        wm + (size_t)3*DMODEL*DMODEL,
                                        wc + (size_t)3*DMODEL*KC,
                                        bo, out, out, out);
}